// round 6
// baseline (speedup 1.0000x reference)
#include <cuda_runtime.h>

// Problem constants (fixed: B=16, T=1024, D=1024, O=10)
#define BB 16
#define TT 1024
#define DD 1024
#define OO 10

#define CTA 256
#define WARPS 8
#define RPW 2                           // rows per warp -> acc = 40 regs
#define RPC (WARPS * RPW)               // 16 rows per CTA
#define KT 128                          // d per stage
#define NKT (DD / KT)                   // 8
#define NSTG 3                          // cp.async stages
#define W_FLOATS (OO * DD)              // 10240 floats = 40 KB
#define STG_FLOATS (RPC * KT)           // 2048 floats = 8 KB
#define SMEM_BYTES ((W_FLOATS + NSTG * STG_FLOATS) * 4)   // 64 KB

__device__ float g_scores[BB * OO * TT];   // [b][o][t]
__device__ float g_wx[BB * OO * TT];       // softmaxed, [b][o][i]

typedef unsigned long long ull;

__device__ __forceinline__ void ffma2(ull& a, ull x, ull y) {
    asm("fma.rn.f32x2 %0, %1, %2, %0;" : "+l"(a) : "l"(x), "l"(y));
}
__device__ __forceinline__ float hsum(ull v) {
    float lo, hi;
    asm("mov.b64 {%0, %1}, %2;" : "=f"(lo), "=f"(hi) : "l"(v));
    return lo + hi;
}
__device__ __forceinline__ void cp16(unsigned s, const void* g) {
    asm volatile("cp.async.cg.shared.global [%0], [%1], 16;" :: "r"(s), "l"(g));
}
__device__ __forceinline__ void cp_commit() {
    asm volatile("cp.async.commit_group;");
}
__device__ __forceinline__ void cp_wait2() {
    asm volatile("cp.async.wait_group 2;");
}

// ---------------------------------------------------------------------------
// Pipelined GEMV: 16 rows x 1024 d per CTA against Wsrc (10 x 1024).
// 3-stage cp.async logits pipeline; W staged once. acc[2][10] packed f32x2.
// ---------------------------------------------------------------------------
__device__ __forceinline__ void gemv_pipe(const float* __restrict__ rows_base,
                                          const float* __restrict__ Wsrc,
                                          float* smem,
                                          ull (&acc)[RPW][OO]) {
    const int tid = threadIdx.x;
    const int warp = tid >> 5;
    const int lane = tid & 31;

    float* Wsm = smem;
    float* stg = smem + W_FLOATS;
    const unsigned sb_w = (unsigned)__cvta_generic_to_shared(Wsm);
    const unsigned sb_s = (unsigned)__cvta_generic_to_shared(stg);

    // Per-thread stage addressing (constant): 512 float4/stage, 2 per thread.
    // chunk j: row = j>>5, col = (j&31)*4
    const int r0 = tid >> 5, c0 = (tid & 31) << 2;       // j = tid
    const int r1 = r0 + 8;                                // j = tid + 256
    const unsigned soff0 = (unsigned)(r0 * KT + c0) * 4;
    const unsigned soff1 = (unsigned)(r1 * KT + c0) * 4;
    const float* g0 = rows_base + (size_t)r0 * DD + c0;
    const float* g1 = rows_base + (size_t)r1 * DD + c0;

    // Prologue: g0 = W + stage0; g1 = stage1; g2 = stage2
    #pragma unroll
    for (int t = 0; t < 10; t++) {
        const int j = tid + t * CTA;
        cp16(sb_w + (unsigned)j * 16, Wsrc + (size_t)j * 4);
    }
    cp16(sb_s + soff0, g0);
    cp16(sb_s + soff1, g1);
    cp_commit();
    #pragma unroll
    for (int s = 1; s < NSTG; s++) {
        cp16(sb_s + (unsigned)(s * STG_FLOATS * 4) + soff0, g0 + s * KT);
        cp16(sb_s + (unsigned)(s * STG_FLOATS * 4) + soff1, g1 + s * KT);
        cp_commit();
    }

    #pragma unroll
    for (int r = 0; r < RPW; r++)
        #pragma unroll
        for (int o = 0; o < OO; o++) acc[r][o] = 0ull;

    const float* myrow = stg + (warp * RPW) * KT + lane * 4;
    const float* wlane = Wsm + lane * 4;

    #pragma unroll
    for (int kt = 0; kt < NKT; kt++) {
        cp_wait2();                 // stage kt resident (and W at kt=0)
        __syncthreads();

        const int slot = kt % NSTG;
        ulonglong2 lg[RPW];
        #pragma unroll
        for (int r = 0; r < RPW; r++)
            lg[r] = *(const ulonglong2*)(myrow + slot * STG_FLOATS + r * KT);

        #pragma unroll
        for (int o = 0; o < OO; o++) {
            const ulonglong2 w2 = *(const ulonglong2*)(wlane + o * DD + kt * KT);
            #pragma unroll
            for (int r = 0; r < RPW; r++) {
                ffma2(acc[r][o], lg[r].x, w2.x);
                ffma2(acc[r][o], lg[r].y, w2.y);
            }
        }

        __syncthreads();            // slot fully consumed before refill
        if (kt + NSTG < NKT) {
            const unsigned sb = sb_s + (unsigned)(slot * STG_FLOATS * 4);
            cp16(sb + soff0, g0 + (kt + NSTG) * KT);
            cp16(sb + soff1, g1 + (kt + NSTG) * KT);
        }
        cp_commit();                // uniform group accounting
    }
}

// Reduce 20 partials across warp; lane0 writes [o][t]-layout results.
__device__ __forceinline__ void reduce_store(ull (&acc)[RPW][OO], int lane,
                                             float* __restrict__ dst,
                                             int t0, float scale,
                                             const float* __restrict__ bias) {
    #pragma unroll
    for (int r = 0; r < RPW; r++)
        #pragma unroll
        for (int o = 0; o < OO; o++) {
            float v = hsum(acc[r][o]);
            #pragma unroll
            for (int s = 16; s > 0; s >>= 1)
                v += __shfl_xor_sync(0xffffffffu, v, s);
            if (lane == 0) {
                if (bias) v = (v + __ldg(&bias[o])) * scale;
                dst[o * TT + t0 + r] = v;
            }
        }
}

// ---------------------------------------------------------------------------
// Kernel 1: scores[b][o][t] = (logits[b,t,:] . W[o,:] + bias[o]) / OO
// Grid 1024 x 256; 16 rows/CTA.
// ---------------------------------------------------------------------------
__global__ __launch_bounds__(CTA, 3) void k_scores(const float* __restrict__ logits,
                                                   const float* __restrict__ W,
                                                   const float* __restrict__ bias) {
    extern __shared__ float smem[];
    const int warp = threadIdx.x >> 5;
    const int lane = threadIdx.x & 31;

    ull acc[RPW][OO];
    gemv_pipe(logits + (size_t)blockIdx.x * RPC * DD, W, smem, acc);

    const int row0 = blockIdx.x * RPC + warp * RPW;
    const int b = row0 / TT;
    reduce_store(acc, lane, g_scores + b * OO * TT, row0 % TT, 1.0f / OO, bias);
}

// ---------------------------------------------------------------------------
// Kernel 2: softmax over t for each (b,o). 160 blocks x 256 threads.
// ---------------------------------------------------------------------------
__global__ __launch_bounds__(256) void k_softmax() {
    const int ro = blockIdx.x;
    const int tid = threadIdx.x;
    const float4 v = ((const float4*)&g_scores[ro * TT])[tid];

    __shared__ float red[8];

    float m = fmaxf(fmaxf(v.x, v.y), fmaxf(v.z, v.w));
    #pragma unroll
    for (int s = 16; s > 0; s >>= 1)
        m = fmaxf(m, __shfl_xor_sync(0xffffffffu, m, s));
    if ((tid & 31) == 0) red[tid >> 5] = m;
    __syncthreads();
    float mall = red[0];
    #pragma unroll
    for (int i = 1; i < 8; i++) mall = fmaxf(mall, red[i]);
    __syncthreads();

    float4 e;
    e.x = __expf(v.x - mall);
    e.y = __expf(v.y - mall);
    e.z = __expf(v.z - mall);
    e.w = __expf(v.w - mall);
    float s4 = e.x + e.y + e.z + e.w;
    #pragma unroll
    for (int s = 16; s > 0; s >>= 1)
        s4 += __shfl_xor_sync(0xffffffffu, s4, s);
    if ((tid & 31) == 0) red[tid >> 5] = s4;
    __syncthreads();
    float sall = 0.0f;
    #pragma unroll
    for (int i = 0; i < 8; i++) sall += red[i];

    const float inv = 1.0f / sall;
    float4 w;
    w.x = e.x * inv; w.y = e.y * inv; w.z = e.z * inv; w.w = e.w * inv;
    ((float4*)&g_wx[ro * TT])[tid] = w;
}

// ---------------------------------------------------------------------------
// Kernel 3: out[b][o][t] = sum_i logits[b,t,i] * g_wx[b][o][i]
// ---------------------------------------------------------------------------
__global__ __launch_bounds__(CTA, 3) void k_out(const float* __restrict__ logits,
                                                float* __restrict__ out) {
    extern __shared__ float smem[];
    const int warp = threadIdx.x >> 5;
    const int lane = threadIdx.x & 31;

    const int row0blk = blockIdx.x * RPC;
    const int b = row0blk / TT;               // 16 rows never cross a batch

    ull acc[RPW][OO];
    gemv_pipe(logits + (size_t)row0blk * DD, g_wx + (size_t)b * W_FLOATS,
              smem, acc);

    const int row0 = row0blk + warp * RPW;
    reduce_store(acc, lane, out + b * OO * TT, row0 % TT, 1.0f, nullptr);
}

// ---------------------------------------------------------------------------
// Launch: inputs per metadata order: logits, decision(unused), W, b
// ---------------------------------------------------------------------------
extern "C" void kernel_launch(void* const* d_in, const int* in_sizes, int n_in,
                              void* d_out, int out_size) {
    const float* logits = (const float*)d_in[0];
    const float* W = (const float*)d_in[2];
    const float* bias = (const float*)d_in[3];
    float* out = (float*)d_out;

    cudaFuncSetAttribute(k_scores, cudaFuncAttributeMaxDynamicSharedMemorySize,
                         SMEM_BYTES);
    cudaFuncSetAttribute(k_out, cudaFuncAttributeMaxDynamicSharedMemorySize,
                         SMEM_BYTES);

    k_scores<<<(BB * TT) / RPC, CTA, SMEM_BYTES>>>(logits, W, bias);
    k_softmax<<<BB * OO, 256>>>();
    k_out<<<(BB * TT) / RPC, CTA, SMEM_BYTES>>>(logits, out);
}

// round 7
// speedup vs baseline: 1.0956x; 1.0956x over previous
#include <cuda_runtime.h>

// Problem constants (fixed: B=16, T=1024, D=1024, O=10)
#define BB 16
#define TT 1024
#define DD 1024
#define OO 10

#define CTA 256
#define WARPS 8
#define RPW 4                           // rows per warp
#define RPC (WARPS * RPW)               // 32 rows per CTA
#define KT 128                          // d per stage
#define NKT (DD / KT)                   // 8
#define NSTG 4                          // cp.async stages (distance-3 pipeline)
#define W_FLOATS (OO * DD)              // 10240 floats = 40 KB
#define STG_FLOATS (RPC * KT)           // 4096 floats = 16 KB
#define SMEM_BYTES ((W_FLOATS + NSTG * STG_FLOATS) * 4)   // 104 KB

__device__ float g_scores[BB * OO * TT];   // [b][o][t]
__device__ float g_wx[BB * OO * TT];       // softmaxed, [b][o][i]

typedef unsigned long long ull;

__device__ __forceinline__ void ffma2(ull& a, ull x, ull y) {
    asm("fma.rn.f32x2 %0, %1, %2, %0;" : "+l"(a) : "l"(x), "l"(y));
}
__device__ __forceinline__ float hsum(ull v) {
    float lo, hi;
    asm("mov.b64 {%0, %1}, %2;" : "=f"(lo), "=f"(hi) : "l"(v));
    return lo + hi;
}
__device__ __forceinline__ void cp16(unsigned s, const void* g) {
    asm volatile("cp.async.cg.shared.global [%0], [%1], 16;" :: "r"(s), "l"(g));
}
__device__ __forceinline__ void cp_commit() {
    asm volatile("cp.async.commit_group;");
}
__device__ __forceinline__ void cp_wait3() {
    asm volatile("cp.async.wait_group 3;");
}

// ---------------------------------------------------------------------------
// Pipelined GEMV: 32 rows x 1024 d per CTA against Wsrc (10 x 1024).
// 4-stage cp.async pipeline (distance 3); W staged once; acc[4][10] f32x2.
// ---------------------------------------------------------------------------
__device__ __forceinline__ void gemv_pipe(const float* __restrict__ rows_base,
                                          const float* __restrict__ Wsrc,
                                          float* smem,
                                          ull (&acc)[RPW][OO]) {
    const int tid = threadIdx.x;
    const int warp = tid >> 5;
    const int lane = tid & 31;

    float* Wsm = smem;
    float* stg = smem + W_FLOATS;
    const unsigned sb_w = (unsigned)__cvta_generic_to_shared(Wsm);
    const unsigned sb_s = (unsigned)__cvta_generic_to_shared(stg);

    // Hoisted per-thread stage addressing: stage = 32 rows x 128 floats =
    // 1024 float4 chunks; 4 per thread. chunk j: row=j>>5, col=(j&31)*4.
    const int c0 = (tid & 31) << 2;
    const int rb = tid >> 5;
    unsigned soff[4];
    const float* gsrc[4];
    #pragma unroll
    for (int i = 0; i < 4; i++) {
        const int r = rb + i * 8;
        soff[i] = (unsigned)(r * KT + c0) * 4;
        gsrc[i] = rows_base + (size_t)r * DD + c0;
    }

    // Prologue: group0 = W + stage0; groups 1..3 = stages 1..3
    #pragma unroll
    for (int t = 0; t < 10; t++) {
        const int j = tid + t * CTA;
        cp16(sb_w + (unsigned)j * 16, Wsrc + (size_t)j * 4);
    }
    #pragma unroll
    for (int i = 0; i < 4; i++) cp16(sb_s + soff[i], gsrc[i]);
    cp_commit();
    #pragma unroll
    for (int s = 1; s < NSTG; s++) {
        #pragma unroll
        for (int i = 0; i < 4; i++)
            cp16(sb_s + (unsigned)(s * STG_FLOATS * 4) + soff[i],
                 gsrc[i] + s * KT);
        cp_commit();
    }

    #pragma unroll
    for (int r = 0; r < RPW; r++)
        #pragma unroll
        for (int o = 0; o < OO; o++) acc[r][o] = 0ull;

    const float* myrow = stg + (warp * RPW) * KT + lane * 4;
    const float* wlane = Wsm + lane * 4;

    #pragma unroll
    for (int kt = 0; kt < NKT; kt++) {
        cp_wait3();                 // stage kt resident (W at kt=0)
        __syncthreads();

        const int slot = kt & (NSTG - 1);
        ulonglong2 lg[RPW];
        #pragma unroll
        for (int r = 0; r < RPW; r++)
            lg[r] = *(const ulonglong2*)(myrow + slot * STG_FLOATS + r * KT);

        #pragma unroll
        for (int o = 0; o < OO; o++) {
            const ulonglong2 w2 = *(const ulonglong2*)(wlane + o * DD + kt * KT);
            #pragma unroll
            for (int r = 0; r < RPW; r++) {
                ffma2(acc[r][o], lg[r].x, w2.x);
                ffma2(acc[r][o], lg[r].y, w2.y);
            }
        }

        __syncthreads();            // slot fully consumed before refill lands
        if (kt + NSTG < NKT) {
            const unsigned sb = sb_s + (unsigned)(slot * STG_FLOATS * 4);
            #pragma unroll
            for (int i = 0; i < 4; i++)
                cp16(sb + soff[i], gsrc[i] + (kt + NSTG) * KT);
        }
        cp_commit();                // uniform group accounting
    }
}

// Reduce 40 partials across warp; lane0 writes [o][t]-layout results.
__device__ __forceinline__ void reduce_store(ull (&acc)[RPW][OO], int lane,
                                             float* __restrict__ dst,
                                             int t0, float scale,
                                             const float* __restrict__ bias) {
    #pragma unroll
    for (int r = 0; r < RPW; r++)
        #pragma unroll
        for (int o = 0; o < OO; o++) {
            float v = hsum(acc[r][o]);
            #pragma unroll
            for (int s = 16; s > 0; s >>= 1)
                v += __shfl_xor_sync(0xffffffffu, v, s);
            if (lane == 0) {
                if (bias) v = (v + __ldg(&bias[o])) * scale;
                dst[o * TT + t0 + r] = v;
            }
        }
}

// ---------------------------------------------------------------------------
// Kernel 1: scores[b][o][t] = (logits[b,t,:] . W[o,:] + bias[o]) / OO
// Grid 512 x 256; 32 rows/CTA.
// ---------------------------------------------------------------------------
__global__ __launch_bounds__(CTA, 2) void k_scores(const float* __restrict__ logits,
                                                   const float* __restrict__ W,
                                                   const float* __restrict__ bias) {
    extern __shared__ float smem[];
    const int warp = threadIdx.x >> 5;
    const int lane = threadIdx.x & 31;

    ull acc[RPW][OO];
    gemv_pipe(logits + (size_t)blockIdx.x * RPC * DD, W, smem, acc);

    const int row0 = blockIdx.x * RPC + warp * RPW;
    const int b = row0 / TT;
    reduce_store(acc, lane, g_scores + b * OO * TT, row0 % TT, 1.0f / OO, bias);
}

// ---------------------------------------------------------------------------
// Kernel 2: softmax over t for each (b,o). 160 blocks x 256 threads.
// ---------------------------------------------------------------------------
__global__ __launch_bounds__(256) void k_softmax() {
    const int ro = blockIdx.x;
    const int tid = threadIdx.x;
    const float4 v = ((const float4*)&g_scores[ro * TT])[tid];

    __shared__ float red[8];

    float m = fmaxf(fmaxf(v.x, v.y), fmaxf(v.z, v.w));
    #pragma unroll
    for (int s = 16; s > 0; s >>= 1)
        m = fmaxf(m, __shfl_xor_sync(0xffffffffu, m, s));
    if ((tid & 31) == 0) red[tid >> 5] = m;
    __syncthreads();
    float mall = red[0];
    #pragma unroll
    for (int i = 1; i < 8; i++) mall = fmaxf(mall, red[i]);
    __syncthreads();

    float4 e;
    e.x = __expf(v.x - mall);
    e.y = __expf(v.y - mall);
    e.z = __expf(v.z - mall);
    e.w = __expf(v.w - mall);
    float s4 = e.x + e.y + e.z + e.w;
    #pragma unroll
    for (int s = 16; s > 0; s >>= 1)
        s4 += __shfl_xor_sync(0xffffffffu, s4, s);
    if ((tid & 31) == 0) red[tid >> 5] = s4;
    __syncthreads();
    float sall = 0.0f;
    #pragma unroll
    for (int i = 0; i < 8; i++) sall += red[i];

    const float inv = 1.0f / sall;
    float4 w;
    w.x = e.x * inv; w.y = e.y * inv; w.z = e.z * inv; w.w = e.w * inv;
    ((float4*)&g_wx[ro * TT])[tid] = w;
}

// ---------------------------------------------------------------------------
// Kernel 3: out[b][o][t] = sum_i logits[b,t,i] * g_wx[b][o][i]
// ---------------------------------------------------------------------------
__global__ __launch_bounds__(CTA, 2) void k_out(const float* __restrict__ logits,
                                                float* __restrict__ out) {
    extern __shared__ float smem[];
    const int warp = threadIdx.x >> 5;
    const int lane = threadIdx.x & 31;

    const int row0blk = blockIdx.x * RPC;
    const int b = row0blk / TT;               // 32 rows never cross a batch

    ull acc[RPW][OO];
    gemv_pipe(logits + (size_t)row0blk * DD, g_wx + (size_t)b * W_FLOATS,
              smem, acc);

    const int row0 = row0blk + warp * RPW;
    reduce_store(acc, lane, out + b * OO * TT, row0 % TT, 1.0f, nullptr);
}

// ---------------------------------------------------------------------------
// Launch: inputs per metadata order: logits, decision(unused), W, b
// ---------------------------------------------------------------------------
extern "C" void kernel_launch(void* const* d_in, const int* in_sizes, int n_in,
                              void* d_out, int out_size) {
    const float* logits = (const float*)d_in[0];
    const float* W = (const float*)d_in[2];
    const float* bias = (const float*)d_in[3];
    float* out = (float*)d_out;

    cudaFuncSetAttribute(k_scores, cudaFuncAttributeMaxDynamicSharedMemorySize,
                         SMEM_BYTES);
    cudaFuncSetAttribute(k_out, cudaFuncAttributeMaxDynamicSharedMemorySize,
                         SMEM_BYTES);

    k_scores<<<(BB * TT) / RPC, CTA, SMEM_BYTES>>>(logits, W, bias);
    k_softmax<<<BB * OO, 256>>>();
    k_out<<<(BB * TT) / RPC, CTA, SMEM_BYTES>>>(logits, out);
}